// round 14
// baseline (speedup 1.0000x reference)
#include <cuda_runtime.h>
#include <math.h>

// Split-KV (flash-decoding) stage-2 merge. B=256, H=32, S=16, D=128, fp32.
//
// R13 = R12 (two 8-deep rounds, the 8.19us winner) + cp.async staging of
// round 2 so ALL 16 row-loads are in flight at once with R12's register
// footprint:
//   * s=0..7  -> registers (LDG.E.128, predicated, front-batched)
//   * s=8..15 -> smem via per-lane cp.async.cg 16B, issued BEFORE the
//     weight math; invalid rows use src-size=0 (HW zero-fill, so w=0
//     rows contribute exact 0 -- no garbage*0 NaN risk)
//   * staging is lane-private (each lane reads only its own slot):
//     no syncwarp/bar needed, just cp.async.wait_group 0
//   * smem 16KB/block (4 warps x 8 rows x 512B) -- not occupancy-binding
// Kept: 1 warp/head, shfl-held weights, cycle-0 LSE/s0/s1 issue, float
// ceil-divs (exact for seq<=8192, splits<=16), half-warp reductions.

#define B_DIM 256
#define H_DIM 32
#define LOG2E 1.4426950408889634f

__global__ __launch_bounds__(128)
void splitkv_merge_kernel(const float* __restrict__ att_out,
                          const float* __restrict__ att_lse,
                          const int*   __restrict__ kv_indptr,
                          const int*   __restrict__ num_kv_splits,
                          float*       __restrict__ out)
{
    __shared__ float4 stage[4][8][32];          // [warp][row s-8][lane] = 16KB

    const unsigned tid  = threadIdx.x;
    const unsigned hid  = (blockIdx.x * 128u + tid) >> 5;    // (b,h)
    const unsigned lane = tid & 31u;
    const unsigned wid  = tid >> 5;                          // warp-in-block
    const unsigned b    = hid >> 5;                          // H == 32

    const float4* __restrict__ src =
        reinterpret_cast<const float4*>(att_out) + hid * 512u + lane;

    // ---- cycle-0 issue group (independent of the geometry chain) ----
    float4 v0 = src[0 * 32];                    // s=0: always valid
    float4 v1 = src[1 * 32];                    // s=1: w=0 kills it if nv==1

    float lse = -INFINITY;
    if (lane < 16u)
        lse = att_lse[hid * 16u + lane];

    const int ip0 = kv_indptr[b];
    const int ip1 = kv_indptr[b + 1];
    const unsigned splits = (unsigned)num_kv_splits[b];

    // ---- geometry via exact float ceil-divs (seq<=8192, splits<=16) ----
    const unsigned seq = (unsigned)(ip1 - ip0);
    const float fseq = __uint2float_rn(seq);
    const unsigned c1 = (unsigned)ceilf(fseq / __uint2float_rn(splits));
    const unsigned per_split = (c1 + 31u) & ~31u;
    const unsigned nv =
        (unsigned)ceilf(fseq / __uint2float_rn(per_split));   // 1..16 prefix

    // ---- round 1 remainder: s=2..7 into registers, predicated ----
    const float4 z = make_float4(0.f, 0.f, 0.f, 0.f);
    float4 v2 = z, v3 = z, v4 = z, v5 = z, v6 = z, v7 = z;
    if (2u < nv) {                              // warp-uniform skip
        v2 = src[2 * 32];
        if (3u < nv) v3 = src[3 * 32];
        if (4u < nv) v4 = src[4 * 32];
        if (5u < nv) v5 = src[5 * 32];
        if (6u < nv) v6 = src[6 * 32];
        if (7u < nv) v7 = src[7 * 32];
    }

    // ---- round 2: s=8..15 staged to smem via cp.async (all in flight now) ----
    const bool has_hi = (8u < nv);
    if (has_hi) {
        const unsigned sbase =
            (unsigned)__cvta_generic_to_shared(&stage[wid][0][lane]);
        #pragma unroll
        for (int s = 8; s < 16; ++s) {
            const unsigned srcsz = ((unsigned)s < nv) ? 16u : 0u;  // zfill invalid
            asm volatile(
                "cp.async.cg.shared.global [%0], [%1], 16, %2;"
                :: "r"(sbase + (unsigned)(s - 8) * 512u),
                   "l"((const void*)(src + s * 32)),
                   "r"(srcsz)
                : "memory");
        }
        asm volatile("cp.async.commit_group;" ::: "memory");
    }

    // ---- weights: 4-step low-half reductions + single broadcast ----
    if (lane >= nv) lse = -INFINITY;

    float m = lse;
    #pragma unroll
    for (int o = 8; o > 0; o >>= 1)
        m = fmaxf(m, __shfl_xor_sync(0xffffffffu, m, o));

    const float w = (lane < nv) ? exp2f((lse - m) * LOG2E) : 0.0f;

    float esum = w;
    #pragma unroll
    for (int o = 8; o > 0; o >>= 1)
        esum += __shfl_xor_sync(0xffffffffu, esum, o);

    const float inv_esum = __shfl_sync(0xffffffffu, 1.0f / esum, 0);

    // ---- consume round 1 (s=0..7): invalid rows have v=0 AND w=0 ----
    float ws = __shfl_sync(0xffffffffu, w, 0);
    float4 acc;
    acc.x = ws * v0.x; acc.y = ws * v0.y;
    acc.z = ws * v0.z; acc.w = ws * v0.w;

#define ACC(S, V)                                            \
    ws = __shfl_sync(0xffffffffu, w, S);                     \
    acc.x = fmaf(ws, V.x, acc.x);                            \
    acc.y = fmaf(ws, V.y, acc.y);                            \
    acc.z = fmaf(ws, V.z, acc.z);                            \
    acc.w = fmaf(ws, V.w, acc.w);

    ACC(1, v1) ACC(2, v2) ACC(3, v3) ACC(4, v4)
    ACC(5, v5) ACC(6, v6) ACC(7, v7)

    // ---- consume round 2 from smem (lane-private slots, no sync) ----
    if (has_hi) {
        asm volatile("cp.async.wait_group 0;" ::: "memory");
        #pragma unroll
        for (int s = 8; s < 16; ++s) {
            const float4 t = stage[wid][s - 8][lane];
            ws = __shfl_sync(0xffffffffu, w, s);
            acc.x = fmaf(ws, t.x, acc.x);
            acc.y = fmaf(ws, t.y, acc.y);
            acc.z = fmaf(ws, t.z, acc.z);
            acc.w = fmaf(ws, t.w, acc.w);
        }
    }
#undef ACC

    acc.x *= inv_esum;
    acc.y *= inv_esum;
    acc.z *= inv_esum;
    acc.w *= inv_esum;

    reinterpret_cast<float4*>(out)[hid * 32u + lane] = acc;
}

extern "C" void kernel_launch(void* const* d_in, const int* in_sizes, int n_in,
                              void* d_out, int out_size)
{
    const float* att_out       = (const float*)d_in[0];
    const float* att_lse       = (const float*)d_in[1];
    // d_in[2] = q, d_in[3] = v_buffer : unused (shape-only in the reference)
    const int*   kv_indptr     = (const int*)d_in[4];
    const int*   num_kv_splits = (const int*)d_in[5];
    float*       out           = (float*)d_out;

    // 8192 head-warps, 4 warps per 128-thread block -> 2048 blocks exact
    splitkv_merge_kernel<<<(B_DIM * H_DIM) / 4, 128>>>(att_out, att_lse,
                                                       kv_indptr, num_kv_splits, out);
}

// round 15
// speedup vs baseline: 1.2266x; 1.2266x over previous
#include <cuda_runtime.h>
#include <math.h>

// Split-KV (flash-decoding) stage-2 merge. B=256, H=32, S=16, D=128, fp32.
//
// R14 = R12 (two 8-deep register rounds, 8.19us best) + buffer-recycled
// round-2 issue so round 2's DRAM latency hides under round-1 FMAs:
//   FMA s0..3  -> v0..v3 dead -> reload v0..v3 = s8..11   (in flight)
//   FMA s4..7  -> v4..v7 dead -> reload v4..v7 = s12..15  (in flight)
//   FMA s8..15 (loads arrived while FMAs ran)
// Same instruction count and SAME peak register set as R12 (8 float4
// buffers; recycling = scoreboard reuse, not new regs). This targets the
// TIMED regime, which R13 proved is L2-warm (bench warm 8.19/10.05 vs
// ncu cold 9.95/9.76 sign flip): no smem staging, no cp.async tax.
// Kept: 1 warp/head, shfl-held weights, exact per-load predication,
// cycle-0 LSE/s0/s1 issue, float ceil-divs (exact for seq<=8192,
// splits<=16), half-warp reductions, 128-thread blocks.

#define B_DIM 256
#define H_DIM 32
#define LOG2E 1.4426950408889634f

__global__ __launch_bounds__(128)
void splitkv_merge_kernel(const float* __restrict__ att_out,
                          const float* __restrict__ att_lse,
                          const int*   __restrict__ kv_indptr,
                          const int*   __restrict__ num_kv_splits,
                          float*       __restrict__ out)
{
    const unsigned hid  = (blockIdx.x * 128u + threadIdx.x) >> 5;   // (b,h)
    const unsigned lane = threadIdx.x & 31u;
    const unsigned b    = hid >> 5;                                 // H == 32

    const float4* __restrict__ src =
        reinterpret_cast<const float4*>(att_out) + hid * 512u + lane;

    // ---- cycle-0 issue group (independent of the geometry chain) ----
    float4 v0 = src[0 * 32];                    // s=0: always valid
    float4 v1 = src[1 * 32];                    // s=1: w=0 kills it if nv==1

    float lse = -INFINITY;
    if (lane < 16u)
        lse = att_lse[hid * 16u + lane];

    const int ip0 = kv_indptr[b];
    const int ip1 = kv_indptr[b + 1];
    const unsigned splits = (unsigned)num_kv_splits[b];

    // ---- geometry via exact float ceil-divs (seq<=8192, splits<=16) ----
    const unsigned seq = (unsigned)(ip1 - ip0);
    const float fseq = __uint2float_rn(seq);
    const unsigned c1 = (unsigned)ceilf(fseq / __uint2float_rn(splits));
    const unsigned per_split = (c1 + 31u) & ~31u;
    const unsigned nv =
        (unsigned)ceilf(fseq / __uint2float_rn(per_split));   // 1..16 prefix

    // ---- round 1 remainder: s=2..7, front-batched, predicated ----
    const float4 z = make_float4(0.f, 0.f, 0.f, 0.f);
    float4 v2 = z, v3 = z, v4 = z, v5 = z, v6 = z, v7 = z;
    if (2u < nv) {                              // warp-uniform skip
        v2 = src[2 * 32];
        if (3u < nv) v3 = src[3 * 32];
        if (4u < nv) v4 = src[4 * 32];
        if (5u < nv) v5 = src[5 * 32];
        if (6u < nv) v6 = src[6 * 32];
        if (7u < nv) v7 = src[7 * 32];
    }

    // ---- weights: 4-step low-half reductions + single broadcast ----
    if (lane >= nv) lse = -INFINITY;

    float m = lse;
    #pragma unroll
    for (int o = 8; o > 0; o >>= 1)
        m = fmaxf(m, __shfl_xor_sync(0xffffffffu, m, o));

    const float w = (lane < nv) ? exp2f((lse - m) * LOG2E) : 0.0f;

    float esum = w;
    #pragma unroll
    for (int o = 8; o > 0; o >>= 1)
        esum += __shfl_xor_sync(0xffffffffu, esum, o);

    const float inv_esum = __shfl_sync(0xffffffffu, 1.0f / esum, 0);

    const bool has_hi = (8u < nv);

#define ACC(S, V)                                            \
    ws = __shfl_sync(0xffffffffu, w, S);                     \
    acc.x = fmaf(ws, V.x, acc.x);                            \
    acc.y = fmaf(ws, V.y, acc.y);                            \
    acc.z = fmaf(ws, V.z, acc.z);                            \
    acc.w = fmaf(ws, V.w, acc.w);

    // ---- consume s0..3, then recycle v0..v3 for s8..11 ----
    float ws = __shfl_sync(0xffffffffu, w, 0);
    float4 acc;
    acc.x = ws * v0.x; acc.y = ws * v0.y;
    acc.z = ws * v0.z; acc.w = ws * v0.w;
    ACC(1, v1) ACC(2, v2) ACC(3, v3)

    if (has_hi) {                               // issue s8..11 NOW (overlap)
        v0 = src[8 * 32];                       // 8 < nv guaranteed here
        v1 = ( 9u < nv) ? src[ 9 * 32] : z;
        v2 = (10u < nv) ? src[10 * 32] : z;
        v3 = (11u < nv) ? src[11 * 32] : z;
    }

    // ---- consume s4..7, then recycle v4..v7 for s12..15 ----
    ACC(4, v4) ACC(5, v5) ACC(6, v6) ACC(7, v7)

    if (has_hi) {                               // issue s12..15 NOW (overlap)
        v4 = (12u < nv) ? src[12 * 32] : z;
        v5 = (13u < nv) ? src[13 * 32] : z;
        v6 = (14u < nv) ? src[14 * 32] : z;
        v7 = (15u < nv) ? src[15 * 32] : z;

        // ---- consume round 2 (loads have been in flight) ----
        ACC( 8, v0) ACC( 9, v1) ACC(10, v2) ACC(11, v3)
        ACC(12, v4) ACC(13, v5) ACC(14, v6) ACC(15, v7)
    }
#undef ACC

    acc.x *= inv_esum;
    acc.y *= inv_esum;
    acc.z *= inv_esum;
    acc.w *= inv_esum;

    reinterpret_cast<float4*>(out)[hid * 32u + lane] = acc;
}

extern "C" void kernel_launch(void* const* d_in, const int* in_sizes, int n_in,
                              void* d_out, int out_size)
{
    const float* att_out       = (const float*)d_in[0];
    const float* att_lse       = (const float*)d_in[1];
    // d_in[2] = q, d_in[3] = v_buffer : unused (shape-only in the reference)
    const int*   kv_indptr     = (const int*)d_in[4];
    const int*   num_kv_splits = (const int*)d_in[5];
    float*       out           = (float*)d_out;

    // 8192 head-warps, 4 warps per 128-thread block -> 2048 blocks exact
    splitkv_merge_kernel<<<(B_DIM * H_DIM) / 4, 128>>>(att_out, att_lse,
                                                       kv_indptr, num_kv_splits, out);
}